// round 16
// baseline (speedup 1.0000x reference)
#include <cuda_runtime.h>
#include <cuda_bf16.h>
#include <cstdint>
#include <math.h>

#define TPB 256          // prep kernels
#define TPBF 512         // FFT-stage kernels

namespace {
constexpr int kNLat = 360;
constexpr int kB    = 2;
constexpr int kC    = 128;
constexpr int kNQ   = 361;                  // nlon/2 + 1
constexpr int kColPad = 768;                // 2*361=722 padded
constexpr int kKin  = 256;                  // [Cr(128) | Ci(128)]
constexpr int kRows = kB * kC * kNLat;      // 92160
constexpr int kBig  = kB * kC * kNQ * kNLat;
constexpr int kOutElems = kB * kC * kNLat * 720;
constexpr int kWElems   = kC * kC * kNLat * 2;
constexpr size_t kCElems = (size_t)kNLat * kColPad * kKin;
constexpr size_t kAElems = (size_t)kNLat * 2 * kC * kKin;
constexpr size_t kYElems = (size_t)kNLat * 2 * kC * kColPad;
constexpr int kNTw = 111;                   // twiddle table (stages use [0,72) and [72,80))
}

// Static device scratch (no allocations anywhere).
__device__ float2        g_bufA[kBig];
__device__ __nv_bfloat16 g_Chi[kCElems];
__device__ __nv_bfloat16 g_Clo[kCElems];
__device__ __nv_bfloat16 g_Ahi[kAElems];
__device__ __nv_bfloat16 g_Alo[kAElems];
__device__ float         g_Y[kYElems];      // [p][half][kout][col]
__device__ float2        g_tw[kNTw];        // stage twiddles e^{-2pi i p/n}
__device__ float2        g_ptw[kNQ];        // pack twiddles e^{-i pi k/360}

__device__ __forceinline__ float2 cmulf(float2 a, float2 b) {
    return make_float2(a.x*b.x - a.y*b.y, a.x*b.y + a.y*b.x);
}
__device__ __forceinline__ float2 caddf(float2 a, float2 b) {
    return make_float2(a.x + b.x, a.y + b.y);
}
__device__ __forceinline__ float2 csubf(float2 a, float2 b) {
    return make_float2(a.x - b.x, a.y - b.y);
}

__device__ __forceinline__ uint32_t smem_u32(const void* p) {
    uint32_t a;
    asm("{ .reg .u64 t; cvta.to.shared.u64 t, %1; cvt.u32.u64 %0, t; }" : "=r"(a) : "l"(p));
    return a;
}
__device__ __forceinline__ void ldsm_x4(uint32_t r[4], uint32_t addr) {
    asm volatile("ldmatrix.sync.aligned.m8n8.x4.shared.b16 {%0,%1,%2,%3}, [%4];"
        : "=r"(r[0]), "=r"(r[1]), "=r"(r[2]), "=r"(r[3]) : "r"(addr));
}
__device__ __forceinline__ void ldsm_x2(uint32_t r[2], uint32_t addr) {
    asm volatile("ldmatrix.sync.aligned.m8n8.x2.shared.b16 {%0,%1}, [%2];"
        : "=r"(r[0]), "=r"(r[1]) : "r"(addr));
}
__device__ __forceinline__ void mma16816(float d[4], const uint32_t a[4], const uint32_t b[2]) {
    asm volatile("mma.sync.aligned.m16n8k16.row.col.f32.bf16.bf16.f32 "
        "{%0,%1,%2,%3}, {%4,%5,%6,%7}, {%8,%9}, {%0,%1,%2,%3};"
        : "+f"(d[0]), "+f"(d[1]), "+f"(d[2]), "+f"(d[3])
        : "r"(a[0]), "r"(a[1]), "r"(a[2]), "r"(a[3]), "r"(b[0]), "r"(b[1]));
}
#define CP16(dst, src) asm volatile("cp.async.cg.shared.global [%0], [%1], 16;" :: "r"(dst), "l"(src))
#define CP_COMMIT()    asm volatile("cp.async.commit_group;" ::: "memory")
#define CP_WAIT1()     asm volatile("cp.async.wait_group 1;" ::: "memory")
#define CP_WAIT0()     asm volatile("cp.async.wait_group 0;" ::: "memory")

// ---------------- twiddle init ----------------
__global__ void k_prepTw()
{
    int t = blockIdx.x * TPB + threadIdx.x;
    if (t < kNTw) {
        int n, p;
        if      (t < 72)  { n = 360; p = t; }
        else if (t < 96)  { n = 72;  p = t - 72; }
        else if (t < 104) { n = 24;  p = t - 96; }
        else if (t < 108) { n = 8;   p = t - 104; }
        else if (t < 110) { n = 4;   p = t - 108; }
        else              { n = 2;   p = 0; }
        float a = -6.283185307179586f * (float)p / (float)n;
        g_tw[t] = make_float2(cosf(a), sinf(a));
    }
    if (t < kNQ) {
        float a = -8.726646259971648e-3f * (float)t;
        g_ptw[t] = make_float2(cosf(a), sinf(a));
    }
}

// ---------------- 3-stage Stockham FFT-360: radices 5, 9, 8 ----------------
template <int L, bool INV, int NT>
__device__ __forceinline__ int fft360(float2 (*buf)[L][361], const float2* s_tw, int tid)
{
    const float sgn = INV ? 1.0f : -1.0f;
    const float SV  = sgn * 0.8660254037844386f;

    auto dft3 = [&](float2 x0, float2 x1, float2 x2,
                    float2& y0, float2& y1, float2& y2) {
        float2 t = caddf(x1, x2);
        float2 d = csubf(x1, x2);
        float2 rr = make_float2(x0.x - 0.5f * t.x, x0.y - 0.5f * t.y);
        y0 = caddf(x0, t);
        y1 = make_float2(rr.x - SV * d.y, rr.y + SV * d.x);
        y2 = make_float2(rr.x + SV * d.y, rr.y - SV * d.x);
    };

    // ---- stage 0: r=5, s=1, n=360, twiddles s_tw[0..72) ----
    for (int t = tid; t < L * 72; t += NT) {
        const int li = t / 72;
        const int u  = t - li * 72;
        const float2* X = buf[0][li];
        float2* Y = buf[1][li];
        float2 w = s_tw[u];
        if (INV) w.y = -w.y;
        float2 w2 = cmulf(w, w);
        float2 w3 = cmulf(w, w2);
        float2 w4 = cmulf(w2, w2);
        float2 a0 = X[u], a1 = X[u + 72], a2 = X[u + 144],
               a3 = X[u + 216], a4 = X[u + 288];
        float2 t1 = caddf(a1, a4), t2 = caddf(a2, a3);
        float2 t3 = csubf(a1, a4), t4 = csubf(a2, a3);
        const float c1 = 0.30901699437494742f, c2 = -0.80901699437494745f;
        const float s1 = 0.95105651629515357f, s2 = 0.58778525229247312f;
        float2 m1 = make_float2(a0.x + c1*t1.x + c2*t2.x, a0.y + c1*t1.y + c2*t2.y);
        float2 m2 = make_float2(a0.x + c2*t1.x + c1*t2.x, a0.y + c2*t1.y + c1*t2.y);
        float2 v1 = make_float2(s1*t3.x + s2*t4.x, s1*t3.y + s2*t4.y);
        float2 v2 = make_float2(s2*t3.x - s1*t4.x, s2*t3.y - s1*t4.y);
        float2 b1 = make_float2(m1.x - sgn*v1.y, m1.y + sgn*v1.x);
        float2 b4 = make_float2(m1.x + sgn*v1.y, m1.y - sgn*v1.x);
        float2 b2 = make_float2(m2.x - sgn*v2.y, m2.y + sgn*v2.x);
        float2 b3 = make_float2(m2.x + sgn*v2.y, m2.y - sgn*v2.x);
        const int base = u * 5;
        Y[base]     = make_float2(a0.x + t1.x + t2.x, a0.y + t1.y + t2.y);
        Y[base + 1] = cmulf(b1, w);
        Y[base + 2] = cmulf(b2, w2);
        Y[base + 3] = cmulf(b3, w3);
        Y[base + 4] = cmulf(b4, w4);
    }
    __syncthreads();

    // ---- stage 1: r=9, s=5, n=72, twiddles s_tw[72..80) ----
    {
        const float2 W91 = make_float2(0.76604444311897804f, sgn * 0.64278760968653933f);
        const float2 W92 = make_float2(0.17364817766693035f, sgn * 0.98480775301220806f);
        const float2 W94 = make_float2(-0.93969262078590838f, sgn * 0.34202014332566873f);
        const float2* twb = s_tw + 72;
        for (int t = tid; t < L * 40; t += NT) {
            const int li = t / 40;
            const int u  = t - li * 40;
            const int q  = u % 5, p = u / 5;
            const float2* X = buf[1][li];
            float2* Y = buf[0][li];
            float2 w = twb[p];
            if (INV) w.y = -w.y;
            float2 w2 = cmulf(w,  w);
            float2 w3 = cmulf(w,  w2);
            float2 w4 = cmulf(w2, w2);
            float2 w5 = cmulf(w2, w3);
            float2 w6 = cmulf(w3, w3);
            float2 w7 = cmulf(w3, w4);
            float2 w8 = cmulf(w4, w4);
            float2 a0 = X[u],       a1 = X[u + 40],  a2 = X[u + 80],
                   a3 = X[u + 120], a4 = X[u + 160], a5 = X[u + 200],
                   a6 = X[u + 240], a7 = X[u + 280], a8 = X[u + 320];
            float2 b00, b01, b02, b10, b11, b12, b20, b21, b22;
            dft3(a0, a3, a6, b00, b01, b02);
            dft3(a1, a4, a7, b10, b11, b12);
            dft3(a2, a5, a8, b20, b21, b22);
            b11 = cmulf(b11, W91);  b21 = cmulf(b21, W92);
            b12 = cmulf(b12, W92);  b22 = cmulf(b22, W94);
            float2 o0, o1, o2, o3, o4, o5, o6, o7, o8;
            dft3(b00, b10, b20, o0, o3, o6);
            dft3(b01, b11, b21, o1, o4, o7);
            dft3(b02, b12, b22, o2, o5, o8);
            const int base = u * 9 - q * 8;     // q + 45*p
            Y[base]      = o0;
            Y[base + 5]  = cmulf(o1, w);
            Y[base + 10] = cmulf(o2, w2);
            Y[base + 15] = cmulf(o3, w3);
            Y[base + 20] = cmulf(o4, w4);
            Y[base + 25] = cmulf(o5, w5);
            Y[base + 30] = cmulf(o6, w6);
            Y[base + 35] = cmulf(o7, w7);
            Y[base + 40] = cmulf(o8, w8);
        }
    }
    __syncthreads();

    // ---- stage 2: r=8, s=45, m=1 -> unit global twiddle ----
    {
        const float H = 0.70710678118654752f;
        const float2 W81 = make_float2(H, sgn * H);
        const float2 W83 = make_float2(-H, sgn * H);
        for (int t = tid; t < L * 45; t += NT) {
            const int li = t / 45;
            const int u  = t - li * 45;
            const float2* X = buf[0][li];
            float2* Y = buf[1][li];
            float2 a0 = X[u],       a1 = X[u + 45],  a2 = X[u + 90],
                   a3 = X[u + 135], a4 = X[u + 180], a5 = X[u + 225],
                   a6 = X[u + 270], a7 = X[u + 315];
            float2 B0 = caddf(a0, a4), C0 = csubf(a0, a4);
            float2 B1 = caddf(a1, a5), C1 = csubf(a1, a5);
            float2 B2 = caddf(a2, a6), C2 = csubf(a2, a6);
            float2 B3 = caddf(a3, a7), C3 = csubf(a3, a7);
            C1 = cmulf(C1, W81);
            C2 = make_float2(-sgn * C2.y, sgn * C2.x);
            C3 = cmulf(C3, W83);
            float2 e0 = caddf(B0, B2), e1 = csubf(B0, B2);
            float2 f0 = caddf(B1, B3), f1 = csubf(B1, B3);
            float2 XB0 = caddf(e0, f0), XB2 = csubf(e0, f0);
            float2 XB1 = make_float2(e1.x - sgn * f1.y, e1.y + sgn * f1.x);
            float2 XB3 = make_float2(e1.x + sgn * f1.y, e1.y - sgn * f1.x);
            float2 g0 = caddf(C0, C2), g1 = csubf(C0, C2);
            float2 h0 = caddf(C1, C3), h1 = csubf(C1, C3);
            float2 XC0 = caddf(g0, h0), XC2 = csubf(g0, h0);
            float2 XC1 = make_float2(g1.x - sgn * h1.y, g1.y + sgn * h1.x);
            float2 XC3 = make_float2(g1.x + sgn * h1.y, g1.y - sgn * h1.x);
            Y[u]       = XB0;
            Y[u + 45]  = XC0;
            Y[u + 90]  = XB1;
            Y[u + 135] = XC1;
            Y[u + 180] = XB2;
            Y[u + 225] = XC2;
            Y[u + 270] = XB3;
            Y[u + 315] = XC3;
        }
    }
    __syncthreads();
    return 1;
}

// ---------------- prepA: smem-transpose, coalesced both sides ----------------
__global__ void __launch_bounds__(TPB) k_prepA(const float* __restrict__ w)
{
    __shared__ float2 tile[8][129];
    const int k  = blockIdx.x;
    const int p0 = blockIdx.y * 8;
    const int tid = threadIdx.x;
    const float2* w2 = (const float2*)w;
    for (int t = tid; t < 1024; t += TPB) {
        int pp = t & 7, i = t >> 3;
        tile[pp][i] = w2[(size_t)(k * 128 + i) * 360 + p0 + pp];
    }
    __syncthreads();
    const float S = 1.0f / 129600.0f;
#pragma unroll
    for (int it = 0; it < 16; ++it) {
        int idx  = it * TPB + tid;       // [pp(3b)][half(1b)][j(8b)]
        int j    = idx & 255;
        int half = (idx >> 8) & 1;
        int pp   = idx >> 9;
        float2 c = tile[pp][j & 127];
        float v;
        if (half == 0) v = (j < 128) ? c.x : -c.y;
        else           v = (j < 128) ? c.y :  c.x;
        v *= S;
        __nv_bfloat16 hi = __float2bfloat16(v);
        size_t o = ((size_t)((p0 + pp) * 2 + half) * 128 + k) * 256 + j;
        g_Ahi[o] = hi;
        g_Alo[o] = __float2bfloat16(v - __bfloat162float(hi));
    }
}

// ---------------- Stage A: rfft-720 along lon; out [b][i][q][lat]; also residual ----------------
__global__ void __launch_bounds__(TPBF, 4) k_stageA(const float2* __restrict__ xin,
                                                    float2* __restrict__ resid)
{
    __shared__ float2 buf[2][8][361];
    __shared__ float2 s_tw[kNTw];
    const int row0 = blockIdx.x * 8;
    const int bi   = row0 / 360;
    const int lat0 = row0 % 360;
    const int tid = threadIdx.x;
    if (tid < kNTw) s_tw[tid] = g_tw[tid];
    for (int e = tid; e < 8 * 360; e += TPBF) {
        int li = e / 360, n = e - li * 360;
        float2 v = xin[(size_t)(row0 + li) * 360 + n];
        buf[0][li][n] = v;
        if (resid) resid[(size_t)(row0 + li) * 360 + n] = v;
    }
    __syncthreads();
    int res = fft360<8, false, TPBF>(buf, s_tw, tid);
    for (int e = tid; e < 8 * 361; e += TPBF) {
        int li = e & 7, k = e >> 3;
        float2 Ck = buf[res][li][(k == 360) ? 0 : k];
        float2 Cm = buf[res][li][(k == 0) ? 0 : (360 - k)];
        float2 E = make_float2(0.5f * (Ck.x + Cm.x), 0.5f * (Ck.y - Cm.y));
        float2 D = make_float2(0.5f * (Ck.x - Cm.x), 0.5f * (Ck.y + Cm.y));
        float2 O = make_float2(D.y, -D.x);
        float2 TO = cmulf(g_ptw[k], O);
        g_bufA[((size_t)bi * 361 + k) * 360 + lat0 + li] =
            make_float2(E.x + TO.x, E.y + TO.y);
    }
}

// ---------------- Stage B: fwd FFT-360 over lat; emit bf16 hi/lo B operand ----------------
// Grid (i0-tile FASTEST, b, q): co-resident blocks complete whole 512B kin-rows
// so L2 write-combines the 32B sectors into full lines.
__global__ void __launch_bounds__(TPBF, 2) k_stageB()
{
    extern __shared__ float2 dsmB[];
    typedef float2 (*BufT)[16][361];
    BufT buf = (BufT)dsmB;
    float2* s_tw = dsmB + 2 * 16 * 361;
    const int i0 = blockIdx.x * 16;
    const int b  = blockIdx.y;
    const int q  = blockIdx.z;
    const int tid = threadIdx.x;
    if (tid < kNTw) s_tw[tid] = g_tw[tid];
    for (int e = tid; e < 16 * 360; e += TPBF) {
        int l = e / 360, p = e - l * 360;
        buf[0][l][p] = g_bufA[((size_t)(b * 128 + i0 + l) * 361 + q) * 360 + p];
    }
    __syncthreads();
    int res = fft360<16, false, TPBF>(buf, s_tw, tid);
    const int col = b * 361 + q;
    for (int e = tid; e < 8 * 360; e += TPBF) {
        int lp = e & 7, pp = e >> 3;
        float2 v0 = buf[res][2 * lp][pp];
        float2 v1 = buf[res][2 * lp + 1][pp];
        union { __nv_bfloat16 h[2]; uint32_t u; } hRe, hIm, lRe, lIm;
        hRe.h[0] = __float2bfloat16(v0.x);
        hRe.h[1] = __float2bfloat16(v1.x);
        hIm.h[0] = __float2bfloat16(v0.y);
        hIm.h[1] = __float2bfloat16(v1.y);
        lRe.h[0] = __float2bfloat16(v0.x - __bfloat162float(hRe.h[0]));
        lRe.h[1] = __float2bfloat16(v1.x - __bfloat162float(hRe.h[1]));
        lIm.h[0] = __float2bfloat16(v0.y - __bfloat162float(hIm.h[0]));
        lIm.h[1] = __float2bfloat16(v1.y - __bfloat162float(hIm.h[1]));
        size_t base = ((size_t)pp * kColPad + col) * kKin + i0 + 2 * lp;
        *(uint32_t*)&g_Chi[base]       = hRe.u;
        *(uint32_t*)&g_Chi[base + 128] = hIm.u;
        *(uint32_t*)&g_Clo[base]       = lRe.u;
        *(uint32_t*)&g_Clo[base + 128] = lIm.u;
    }
}

// ---------------- Stage C: mma.sync bf16 split GEMM, half-merged ----------------
// One 512-thread CTA computes BOTH halves at (p, col-tile): warps 0-7 half0,
// warps 8-15 half1; the B tile (identical across halves) is loaded ONCE.
// acc += Ahi*Bhi + Alo*Bhi + Ahi*Blo.
// Stage smem (80B rows): A0hi[0) A0lo[10240) A1hi[20480) A1lo[30720)
//                        Bhi[40960) Blo[46080); stage size 51200, 2 stages.
__global__ void __launch_bounds__(512) k_gemm_mma()
{
    extern __shared__ char dsmG[];
    const uint32_t sbase = smem_u32(dsmG);

    const int p    = blockIdx.y;
    const int c0   = blockIdx.x * 64;
    const int tid  = threadIdx.x;
    const int wid  = tid >> 5;
    const int lid  = tid & 31;
    const int half = wid >> 3;
    const int w8   = wid & 7;
    const int wm   = w8 & 3;
    const int wn   = w8 >> 2;

    const __nv_bfloat16* Ah0 = g_Ahi + (size_t)(p * 2 + 0) * 128 * kKin;
    const __nv_bfloat16* Al0 = g_Alo + (size_t)(p * 2 + 0) * 128 * kKin;
    const __nv_bfloat16* Ah1 = g_Ahi + (size_t)(p * 2 + 1) * 128 * kKin;
    const __nv_bfloat16* Al1 = g_Alo + (size_t)(p * 2 + 1) * 128 * kKin;
    const __nv_bfloat16* Bh  = g_Chi + ((size_t)p * kColPad + c0) * kKin;
    const __nv_bfloat16* Bl  = g_Clo + ((size_t)p * kColPad + c0) * kKin;

    const int arow = tid >> 2, aj = tid & 3;          // 128 rows x 4 chunks
    const int t2 = tid & 255;
    const int brow = t2 >> 2, bj = t2 & 3;            // 64 rows x 4 chunks

    auto issue = [&](int kc, int s) {
        const int kg = kc * 32;
        const uint32_t st = sbase + s * 51200;
        size_t o = (size_t)arow * kKin + kg + aj * 8;
        uint32_t d = st + arow * 80 + aj * 16;
        CP16(d,          Ah0 + o);
        CP16(d + 10240,  Al0 + o);
        CP16(d + 20480,  Ah1 + o);
        CP16(d + 30720,  Al1 + o);
        size_t ob = (size_t)brow * kKin + kg + bj * 8;
        uint32_t db = st + 40960 + brow * 80 + bj * 16;
        if (tid < 256) CP16(db, Bh + ob);
        else           CP16(db + 5120, Bl + ob);
        CP_COMMIT();
    };

    float acc[2][4][4];
#pragma unroll
    for (int f = 0; f < 2; ++f)
#pragma unroll
        for (int g = 0; g < 4; ++g)
#pragma unroll
            for (int v = 0; v < 4; ++v) acc[f][g][v] = 0.f;

    issue(0, 0);

    for (int kc = 0; kc < 8; ++kc) {
        const int s = kc & 1;
        if (kc < 7) issue(kc + 1, s ^ 1);
        if (kc < 7) CP_WAIT1(); else CP_WAIT0();
        __syncthreads();

        const uint32_t uAh = sbase + s * 51200 + half * 20480;
        const uint32_t uAl = uAh + 10240;
        const uint32_t uBh = sbase + s * 51200 + 40960;
        const uint32_t uBl = uBh + 5120;
#pragma unroll
        for (int ks = 0; ks < 2; ++ks) {
            const int kb = ks * 16;
            uint32_t ahi[2][4], alo[2][4], bhi[4][2], blo[4][2];
            const int ar = (lid & 15);
            const int akof = kb + ((lid >> 4) << 3);
#pragma unroll
            for (int f = 0; f < 2; ++f) {
                const int m0 = wm * 32 + f * 16;
                uint32_t off = ((m0 + ar) * 40 + akof) * 2;
                ldsm_x4(ahi[f], uAh + off);
                ldsm_x4(alo[f], uAl + off);
            }
            const int br2 = (lid & 7);
            const int bkof = kb + (((lid >> 3) & 1) << 3);
#pragma unroll
            for (int g = 0; g < 4; ++g) {
                const int n0 = wn * 32 + g * 8;
                uint32_t off = ((n0 + br2) * 40 + bkof) * 2;
                ldsm_x2(bhi[g], uBh + off);
                ldsm_x2(blo[g], uBl + off);
            }
#pragma unroll
            for (int f = 0; f < 2; ++f)
#pragma unroll
                for (int g = 0; g < 4; ++g) {
                    mma16816(acc[f][g], ahi[f], bhi[g]);
                    mma16816(acc[f][g], alo[f], bhi[g]);
                    mma16816(acc[f][g], ahi[f], blo[g]);
                }
        }
        __syncthreads();
    }

    const size_t yrow = (size_t)(p * 2 + half) * 128;
    const int gr = lid >> 2, tg = lid & 3;
#pragma unroll
    for (int f = 0; f < 2; ++f) {
        const int r0 = wm * 32 + f * 16 + gr;
#pragma unroll
        for (int g = 0; g < 4; ++g) {
            const int col = c0 + wn * 32 + g * 8 + 2 * tg;
            if (col < 722) {
                *(float2*)&g_Y[(yrow + r0) * kColPad + col] =
                    make_float2(acc[f][g][0], acc[f][g][1]);
                *(float2*)&g_Y[(yrow + r0 + 8) * kColPad + col] =
                    make_float2(acc[f][g][2], acc[f][g][3]);
            }
        }
    }
}

// ---------------- Stage D: inverse FFT-360 over lat; out [b][k][lat][q] ----------------
__global__ void __launch_bounds__(TPBF, 4) k_stageD()
{
    __shared__ float2 buf[2][8][361];
    __shared__ float2 s_tw[kNTw];
    const int q0 = blockIdx.x * 8;
    const int bk = blockIdx.y;
    const int b = bk >> 7, k = bk & 127;
    const int tid = threadIdx.x;
    if (tid < kNTw) s_tw[tid] = g_tw[tid];
    for (int e = tid; e < 8 * 360; e += TPBF) {
        int qi = e & 7, p = e >> 3;
        int q = q0 + qi;
        if (q < kNQ) {
            int col = b * 361 + q;
            float yr = g_Y[((size_t)(p * 2 + 0) * 128 + k) * kColPad + col];
            float yi = g_Y[((size_t)(p * 2 + 1) * 128 + k) * kColPad + col];
            buf[0][qi][p] = make_float2(yr, yi);
        } else buf[0][qi][p] = make_float2(0.f, 0.f);
    }
    __syncthreads();
    int res = fft360<8, true, TPBF>(buf, s_tw, tid);
    for (int e = tid; e < 8 * 360; e += TPBF) {
        int qi = e & 7, p = e >> 3;
        int q = q0 + qi;
        if (q < kNQ)
            g_bufA[((size_t)bk * 360 + p) * 361 + q] = buf[res][qi][p];
    }
}

// ---------------- Stage E: inverse real-pack + inverse cfft-360 -> 720 samples ----------------
__global__ void __launch_bounds__(TPBF, 4) k_stageE(float2* __restrict__ out)
{
    __shared__ float2 buf[2][8][361];
    __shared__ float2 s_tw[kNTw];
    const int row0 = blockIdx.x * 8;
    const int tid = threadIdx.x;
    if (tid < kNTw) s_tw[tid] = g_tw[tid];
    for (int e = tid; e < 8 * 360; e += TPBF) {
        int li = e / 360, k = e - li * 360;
        const float2* src = g_bufA + (size_t)(row0 + li) * 361;
        float2 X1 = src[k];
        float2 X2 = src[360 - k];
        if (k == 0) { X1.y = 0.f; X2.y = 0.f; }   // irfft drops Im(DC), Im(Nyquist)
        float2 E = make_float2(0.5f * (X1.x + X2.x), 0.5f * (X1.y - X2.y));
        float2 D = make_float2(0.5f * (X1.x - X2.x), 0.5f * (X1.y + X2.y));
        float2 pw = g_ptw[k]; pw.y = -pw.y;       // e^{+i pi k/360}
        float2 O = cmulf(pw, D);
        buf[0][li][k] = make_float2(E.x - O.y, E.y + O.x);
    }
    __syncthreads();
    int res = fft360<8, true, TPBF>(buf, s_tw, tid);
    for (int e = tid; e < 8 * 360; e += TPBF) {
        int li = e / 360, n = e - li * 360;
        out[(size_t)(row0 + li) * 360 + n] = buf[res][li][n];
    }
}

extern "C" void kernel_launch(void* const* d_in, const int* in_sizes, int n_in,
                              void* d_out, int out_size)
{
    const float* x = nullptr;
    const float* w = nullptr;
    for (int i = 0; i < n_in; ++i) {
        if (in_sizes[i] == kOutElems)      x = (const float*)d_in[i];
        else if (in_sizes[i] == kWElems)   w = (const float*)d_in[i];
    }
    if (!x) x = (const float*)d_in[0];
    if (!w) w = (const float*)d_in[1];

    constexpr int kSmemB = (2 * 16 * 361 + kNTw) * (int)sizeof(float2);  // 93304
    constexpr int kSmemG = 2 * 51200;                                    // 102400
    cudaFuncSetAttribute(k_stageB,   cudaFuncAttributeMaxDynamicSharedMemorySize, kSmemB);
    cudaFuncSetAttribute(k_gemm_mma, cudaFuncAttributeMaxDynamicSharedMemorySize, kSmemG);

    float2* resid = (out_size >= 2 * kOutElems)
                  ? (float2*)((float*)d_out + kOutElems) : nullptr;

    k_prepTw<<< 2, TPB >>>();
    k_prepA <<< dim3(128, 45), TPB >>> (w);
    k_stageA<<< kRows / 8, TPBF >>>((const float2*)x, resid);
    k_stageB<<< dim3(8, 2, 361), TPBF, kSmemB >>>();
    k_gemm_mma<<< dim3(12, 360), 512, kSmemG >>>();
    k_stageD<<< dim3(46, kB * kC), TPBF >>>();
    k_stageE<<< kRows / 8, TPBF >>>((float2*)d_out);
}

// round 17
// speedup vs baseline: 1.1037x; 1.1037x over previous
#include <cuda_runtime.h>
#include <cuda_bf16.h>
#include <cstdint>
#include <math.h>

#define TPB 256          // prep kernels
#define TPBF 512         // FFT-stage kernels

namespace {
constexpr int kNLat = 360;
constexpr int kB    = 2;
constexpr int kC    = 128;
constexpr int kNQ   = 361;                  // nlon/2 + 1
constexpr int kColPad = 768;                // 2*361=722 padded
constexpr int kKin  = 256;                  // [Cr(128) | Ci(128)]
constexpr int kRows = kB * kC * kNLat;      // 92160
constexpr int kBig  = kB * kC * kNQ * kNLat;
constexpr int kOutElems = kB * kC * kNLat * 720;
constexpr int kWElems   = kC * kC * kNLat * 2;
constexpr size_t kCElems = (size_t)kNLat * kColPad * kKin;
constexpr size_t kAElems = (size_t)kNLat * 2 * kC * kKin;
constexpr size_t kYElems = (size_t)kNLat * 2 * kC * kColPad;
constexpr int kNTw = 111;                   // twiddle table (stages use [0,72) and [72,80))
}

// Static device scratch (no allocations anywhere).
__device__ float2        g_bufA[kBig];
__device__ __nv_bfloat16 g_Chi[kCElems];
__device__ __nv_bfloat16 g_Clo[kCElems];
__device__ __nv_bfloat16 g_Ahi[kAElems];
__device__ __nv_bfloat16 g_Alo[kAElems];
__device__ float         g_Y[kYElems];      // [p][half][kout][col]
__device__ float2        g_tw[kNTw];        // stage twiddles e^{-2pi i p/n}
__device__ float2        g_ptw[kNQ];        // pack twiddles e^{-i pi k/360}

__device__ __forceinline__ float2 cmulf(float2 a, float2 b) {
    return make_float2(a.x*b.x - a.y*b.y, a.x*b.y + a.y*b.x);
}
__device__ __forceinline__ float2 caddf(float2 a, float2 b) {
    return make_float2(a.x + b.x, a.y + b.y);
}
__device__ __forceinline__ float2 csubf(float2 a, float2 b) {
    return make_float2(a.x - b.x, a.y - b.y);
}

__device__ __forceinline__ uint32_t smem_u32(const void* p) {
    uint32_t a;
    asm("{ .reg .u64 t; cvta.to.shared.u64 t, %1; cvt.u32.u64 %0, t; }" : "=r"(a) : "l"(p));
    return a;
}
__device__ __forceinline__ void ldsm_x4(uint32_t r[4], uint32_t addr) {
    asm volatile("ldmatrix.sync.aligned.m8n8.x4.shared.b16 {%0,%1,%2,%3}, [%4];"
        : "=r"(r[0]), "=r"(r[1]), "=r"(r[2]), "=r"(r[3]) : "r"(addr));
}
__device__ __forceinline__ void ldsm_x2(uint32_t r[2], uint32_t addr) {
    asm volatile("ldmatrix.sync.aligned.m8n8.x2.shared.b16 {%0,%1}, [%2];"
        : "=r"(r[0]), "=r"(r[1]) : "r"(addr));
}
__device__ __forceinline__ void mma16816(float d[4], const uint32_t a[4], const uint32_t b[2]) {
    asm volatile("mma.sync.aligned.m16n8k16.row.col.f32.bf16.bf16.f32 "
        "{%0,%1,%2,%3}, {%4,%5,%6,%7}, {%8,%9}, {%0,%1,%2,%3};"
        : "+f"(d[0]), "+f"(d[1]), "+f"(d[2]), "+f"(d[3])
        : "r"(a[0]), "r"(a[1]), "r"(a[2]), "r"(a[3]), "r"(b[0]), "r"(b[1]));
}
#define CP16(dst, src) asm volatile("cp.async.cg.shared.global [%0], [%1], 16;" :: "r"(dst), "l"(src))
#define CP_COMMIT()    asm volatile("cp.async.commit_group;" ::: "memory")
#define CP_WAIT1()     asm volatile("cp.async.wait_group 1;" ::: "memory")
#define CP_WAIT0()     asm volatile("cp.async.wait_group 0;" ::: "memory")

// ---------------- twiddle init ----------------
__global__ void k_prepTw()
{
    int t = blockIdx.x * TPB + threadIdx.x;
    if (t < kNTw) {
        int n, p;
        if      (t < 72)  { n = 360; p = t; }
        else if (t < 96)  { n = 72;  p = t - 72; }
        else if (t < 104) { n = 24;  p = t - 96; }
        else if (t < 108) { n = 8;   p = t - 104; }
        else if (t < 110) { n = 4;   p = t - 108; }
        else              { n = 2;   p = 0; }
        float a = -6.283185307179586f * (float)p / (float)n;
        g_tw[t] = make_float2(cosf(a), sinf(a));
    }
    if (t < kNQ) {
        float a = -8.726646259971648e-3f * (float)t;
        g_ptw[t] = make_float2(cosf(a), sinf(a));
    }
}

// ---------------- 3-stage Stockham FFT-360: radices 5, 9, 8 ----------------
template <int L, bool INV, int NT>
__device__ __forceinline__ int fft360(float2 (*buf)[L][361], const float2* s_tw, int tid)
{
    const float sgn = INV ? 1.0f : -1.0f;
    const float SV  = sgn * 0.8660254037844386f;

    auto dft3 = [&](float2 x0, float2 x1, float2 x2,
                    float2& y0, float2& y1, float2& y2) {
        float2 t = caddf(x1, x2);
        float2 d = csubf(x1, x2);
        float2 rr = make_float2(x0.x - 0.5f * t.x, x0.y - 0.5f * t.y);
        y0 = caddf(x0, t);
        y1 = make_float2(rr.x - SV * d.y, rr.y + SV * d.x);
        y2 = make_float2(rr.x + SV * d.y, rr.y - SV * d.x);
    };

    // ---- stage 0: r=5, s=1, n=360, twiddles s_tw[0..72) ----
    for (int t = tid; t < L * 72; t += NT) {
        const int li = t / 72;
        const int u  = t - li * 72;
        const float2* X = buf[0][li];
        float2* Y = buf[1][li];
        float2 w = s_tw[u];
        if (INV) w.y = -w.y;
        float2 w2 = cmulf(w, w);
        float2 w3 = cmulf(w, w2);
        float2 w4 = cmulf(w2, w2);
        float2 a0 = X[u], a1 = X[u + 72], a2 = X[u + 144],
               a3 = X[u + 216], a4 = X[u + 288];
        float2 t1 = caddf(a1, a4), t2 = caddf(a2, a3);
        float2 t3 = csubf(a1, a4), t4 = csubf(a2, a3);
        const float c1 = 0.30901699437494742f, c2 = -0.80901699437494745f;
        const float s1 = 0.95105651629515357f, s2 = 0.58778525229247312f;
        float2 m1 = make_float2(a0.x + c1*t1.x + c2*t2.x, a0.y + c1*t1.y + c2*t2.y);
        float2 m2 = make_float2(a0.x + c2*t1.x + c1*t2.x, a0.y + c2*t1.y + c1*t2.y);
        float2 v1 = make_float2(s1*t3.x + s2*t4.x, s1*t3.y + s2*t4.y);
        float2 v2 = make_float2(s2*t3.x - s1*t4.x, s2*t3.y - s1*t4.y);
        float2 b1 = make_float2(m1.x - sgn*v1.y, m1.y + sgn*v1.x);
        float2 b4 = make_float2(m1.x + sgn*v1.y, m1.y - sgn*v1.x);
        float2 b2 = make_float2(m2.x - sgn*v2.y, m2.y + sgn*v2.x);
        float2 b3 = make_float2(m2.x + sgn*v2.y, m2.y - sgn*v2.x);
        const int base = u * 5;
        Y[base]     = make_float2(a0.x + t1.x + t2.x, a0.y + t1.y + t2.y);
        Y[base + 1] = cmulf(b1, w);
        Y[base + 2] = cmulf(b2, w2);
        Y[base + 3] = cmulf(b3, w3);
        Y[base + 4] = cmulf(b4, w4);
    }
    __syncthreads();

    // ---- stage 1: r=9, s=5, n=72, twiddles s_tw[72..80) ----
    {
        const float2 W91 = make_float2(0.76604444311897804f, sgn * 0.64278760968653933f);
        const float2 W92 = make_float2(0.17364817766693035f, sgn * 0.98480775301220806f);
        const float2 W94 = make_float2(-0.93969262078590838f, sgn * 0.34202014332566873f);
        const float2* twb = s_tw + 72;
        for (int t = tid; t < L * 40; t += NT) {
            const int li = t / 40;
            const int u  = t - li * 40;
            const int q  = u % 5, p = u / 5;
            const float2* X = buf[1][li];
            float2* Y = buf[0][li];
            float2 w = twb[p];
            if (INV) w.y = -w.y;
            float2 w2 = cmulf(w,  w);
            float2 w3 = cmulf(w,  w2);
            float2 w4 = cmulf(w2, w2);
            float2 w5 = cmulf(w2, w3);
            float2 w6 = cmulf(w3, w3);
            float2 w7 = cmulf(w3, w4);
            float2 w8 = cmulf(w4, w4);
            float2 a0 = X[u],       a1 = X[u + 40],  a2 = X[u + 80],
                   a3 = X[u + 120], a4 = X[u + 160], a5 = X[u + 200],
                   a6 = X[u + 240], a7 = X[u + 280], a8 = X[u + 320];
            float2 b00, b01, b02, b10, b11, b12, b20, b21, b22;
            dft3(a0, a3, a6, b00, b01, b02);
            dft3(a1, a4, a7, b10, b11, b12);
            dft3(a2, a5, a8, b20, b21, b22);
            b11 = cmulf(b11, W91);  b21 = cmulf(b21, W92);
            b12 = cmulf(b12, W92);  b22 = cmulf(b22, W94);
            float2 o0, o1, o2, o3, o4, o5, o6, o7, o8;
            dft3(b00, b10, b20, o0, o3, o6);
            dft3(b01, b11, b21, o1, o4, o7);
            dft3(b02, b12, b22, o2, o5, o8);
            const int base = u * 9 - q * 8;     // q + 45*p
            Y[base]      = o0;
            Y[base + 5]  = cmulf(o1, w);
            Y[base + 10] = cmulf(o2, w2);
            Y[base + 15] = cmulf(o3, w3);
            Y[base + 20] = cmulf(o4, w4);
            Y[base + 25] = cmulf(o5, w5);
            Y[base + 30] = cmulf(o6, w6);
            Y[base + 35] = cmulf(o7, w7);
            Y[base + 40] = cmulf(o8, w8);
        }
    }
    __syncthreads();

    // ---- stage 2: r=8, s=45, m=1 -> unit global twiddle ----
    {
        const float H = 0.70710678118654752f;
        const float2 W81 = make_float2(H, sgn * H);
        const float2 W83 = make_float2(-H, sgn * H);
        for (int t = tid; t < L * 45; t += NT) {
            const int li = t / 45;
            const int u  = t - li * 45;
            const float2* X = buf[0][li];
            float2* Y = buf[1][li];
            float2 a0 = X[u],       a1 = X[u + 45],  a2 = X[u + 90],
                   a3 = X[u + 135], a4 = X[u + 180], a5 = X[u + 225],
                   a6 = X[u + 270], a7 = X[u + 315];
            float2 B0 = caddf(a0, a4), C0 = csubf(a0, a4);
            float2 B1 = caddf(a1, a5), C1 = csubf(a1, a5);
            float2 B2 = caddf(a2, a6), C2 = csubf(a2, a6);
            float2 B3 = caddf(a3, a7), C3 = csubf(a3, a7);
            C1 = cmulf(C1, W81);
            C2 = make_float2(-sgn * C2.y, sgn * C2.x);
            C3 = cmulf(C3, W83);
            float2 e0 = caddf(B0, B2), e1 = csubf(B0, B2);
            float2 f0 = caddf(B1, B3), f1 = csubf(B1, B3);
            float2 XB0 = caddf(e0, f0), XB2 = csubf(e0, f0);
            float2 XB1 = make_float2(e1.x - sgn * f1.y, e1.y + sgn * f1.x);
            float2 XB3 = make_float2(e1.x + sgn * f1.y, e1.y - sgn * f1.x);
            float2 g0 = caddf(C0, C2), g1 = csubf(C0, C2);
            float2 h0 = caddf(C1, C3), h1 = csubf(C1, C3);
            float2 XC0 = caddf(g0, h0), XC2 = csubf(g0, h0);
            float2 XC1 = make_float2(g1.x - sgn * h1.y, g1.y + sgn * h1.x);
            float2 XC3 = make_float2(g1.x + sgn * h1.y, g1.y - sgn * h1.x);
            Y[u]       = XB0;
            Y[u + 45]  = XC0;
            Y[u + 90]  = XB1;
            Y[u + 135] = XC1;
            Y[u + 180] = XB2;
            Y[u + 225] = XC2;
            Y[u + 270] = XB3;
            Y[u + 315] = XC3;
        }
    }
    __syncthreads();
    return 1;
}

// ---------------- prepA: smem-transpose, coalesced both sides ----------------
__global__ void __launch_bounds__(TPB) k_prepA(const float* __restrict__ w)
{
    __shared__ float2 tile[8][129];
    const int k  = blockIdx.x;
    const int p0 = blockIdx.y * 8;
    const int tid = threadIdx.x;
    const float2* w2 = (const float2*)w;
    for (int t = tid; t < 1024; t += TPB) {
        int pp = t & 7, i = t >> 3;
        tile[pp][i] = w2[(size_t)(k * 128 + i) * 360 + p0 + pp];
    }
    __syncthreads();
    const float S = 1.0f / 129600.0f;
#pragma unroll
    for (int it = 0; it < 16; ++it) {
        int idx  = it * TPB + tid;       // [pp(3b)][half(1b)][j(8b)]
        int j    = idx & 255;
        int half = (idx >> 8) & 1;
        int pp   = idx >> 9;
        float2 c = tile[pp][j & 127];
        float v;
        if (half == 0) v = (j < 128) ? c.x : -c.y;
        else           v = (j < 128) ? c.y :  c.x;
        v *= S;
        __nv_bfloat16 hi = __float2bfloat16(v);
        size_t o = ((size_t)((p0 + pp) * 2 + half) * 128 + k) * 256 + j;
        g_Ahi[o] = hi;
        g_Alo[o] = __float2bfloat16(v - __bfloat162float(hi));
    }
}

// ---------------- Stage A: rfft-720 along lon; out [b][i][q][lat]; also residual ----------------
__global__ void __launch_bounds__(TPBF, 4) k_stageA(const float4* __restrict__ xin4,
                                                    float4* __restrict__ resid4)
{
    __shared__ float2 buf[2][8][361];
    __shared__ float2 s_tw[kNTw];
    const int row0 = blockIdx.x * 8;
    const int bi   = row0 / 360;
    const int lat0 = row0 % 360;
    const int tid = threadIdx.x;
    if (tid < kNTw) s_tw[tid] = g_tw[tid];
    for (int e = tid; e < 8 * 180; e += TPBF) {
        int li = e / 180, j = e - li * 180;
        float4 v = xin4[(size_t)(row0 + li) * 180 + j];
        buf[0][li][2 * j]     = make_float2(v.x, v.y);
        buf[0][li][2 * j + 1] = make_float2(v.z, v.w);
        if (resid4) resid4[(size_t)(row0 + li) * 180 + j] = v;
    }
    __syncthreads();
    int res = fft360<8, false, TPBF>(buf, s_tw, tid);
    for (int e = tid; e < 8 * 361; e += TPBF) {
        int li = e & 7, k = e >> 3;
        float2 Ck = buf[res][li][(k == 360) ? 0 : k];
        float2 Cm = buf[res][li][(k == 0) ? 0 : (360 - k)];
        float2 E = make_float2(0.5f * (Ck.x + Cm.x), 0.5f * (Ck.y - Cm.y));
        float2 D = make_float2(0.5f * (Ck.x - Cm.x), 0.5f * (Ck.y + Cm.y));
        float2 O = make_float2(D.y, -D.x);
        float2 TO = cmulf(g_ptw[k], O);
        g_bufA[((size_t)bi * 361 + k) * 360 + lat0 + li] =
            make_float2(E.x + TO.x, E.y + TO.y);
    }
}

// ---------------- Stage B: fwd FFT-360 over lat; emit bf16 hi/lo B operand ----------------
// Grid (i0-tile FASTEST, b, q): co-resident blocks complete whole 512B kin-rows
// so L2 write-combines the 32B sectors into full lines. float4 input loads.
__global__ void __launch_bounds__(TPBF, 2) k_stageB()
{
    extern __shared__ float2 dsmB[];
    typedef float2 (*BufT)[16][361];
    BufT buf = (BufT)dsmB;
    float2* s_tw = dsmB + 2 * 16 * 361;
    const int i0 = blockIdx.x * 16;
    const int b  = blockIdx.y;
    const int q  = blockIdx.z;
    const int tid = threadIdx.x;
    if (tid < kNTw) s_tw[tid] = g_tw[tid];
    for (int e = tid; e < 16 * 180; e += TPBF) {
        int l = e / 180, j = e - l * 180;
        float4 v = *(const float4*)&g_bufA[((size_t)(b * 128 + i0 + l) * 361 + q) * 360 + 2 * j];
        buf[0][l][2 * j]     = make_float2(v.x, v.y);
        buf[0][l][2 * j + 1] = make_float2(v.z, v.w);
    }
    __syncthreads();
    int res = fft360<16, false, TPBF>(buf, s_tw, tid);
    const int col = b * 361 + q;
    for (int e = tid; e < 8 * 360; e += TPBF) {
        int lp = e & 7, pp = e >> 3;
        float2 v0 = buf[res][2 * lp][pp];
        float2 v1 = buf[res][2 * lp + 1][pp];
        union { __nv_bfloat16 h[2]; uint32_t u; } hRe, hIm, lRe, lIm;
        hRe.h[0] = __float2bfloat16(v0.x);
        hRe.h[1] = __float2bfloat16(v1.x);
        hIm.h[0] = __float2bfloat16(v0.y);
        hIm.h[1] = __float2bfloat16(v1.y);
        lRe.h[0] = __float2bfloat16(v0.x - __bfloat162float(hRe.h[0]));
        lRe.h[1] = __float2bfloat16(v1.x - __bfloat162float(hRe.h[1]));
        lIm.h[0] = __float2bfloat16(v0.y - __bfloat162float(hIm.h[0]));
        lIm.h[1] = __float2bfloat16(v1.y - __bfloat162float(hIm.h[1]));
        size_t base = ((size_t)pp * kColPad + col) * kKin + i0 + 2 * lp;
        *(uint32_t*)&g_Chi[base]       = hRe.u;
        *(uint32_t*)&g_Chi[base + 128] = hIm.u;
        *(uint32_t*)&g_Clo[base]       = lRe.u;
        *(uint32_t*)&g_Clo[base + 128] = lIm.u;
    }
}

// ---------------- Stage C: mma.sync bf16 split GEMM (R11/R15-proven config) ----------------
__global__ void __launch_bounds__(256) k_gemm_mma()
{
    extern __shared__ char dsmG[];
    const uint32_t sbase = smem_u32(dsmG);

    const int p    = blockIdx.z;
    const int half = blockIdx.y;
    const int c0   = blockIdx.x * 64;
    const int tid  = threadIdx.x;
    const int wid  = tid >> 5;
    const int lid  = tid & 31;
    const int wm   = wid & 3;
    const int wn   = wid >> 2;

    const __nv_bfloat16* Ah = g_Ahi + (size_t)(p * 2 + half) * 128 * kKin;
    const __nv_bfloat16* Al = g_Alo + (size_t)(p * 2 + half) * 128 * kKin;
    const __nv_bfloat16* Bh = g_Chi + ((size_t)p * kColPad + c0) * kKin;
    const __nv_bfloat16* Bl = g_Clo + ((size_t)p * kColPad + c0) * kKin;

    const int ar0 = tid >> 2, aj = tid & 3;
    const int br  = tid >> 2, bj = tid & 3;

    auto issue = [&](int kc, int s) {
        const int kg = kc * 32;
        const uint32_t st = sbase + s * 30720;
#pragma unroll
        for (int it = 0; it < 2; ++it) {
            int row = ar0 + it * 64;
            const __nv_bfloat16* sa = Ah + (size_t)row * kKin + kg + aj * 8;
            const __nv_bfloat16* sl = Al + (size_t)row * kKin + kg + aj * 8;
            uint32_t d = st + row * 80 + aj * 16;
            CP16(d, sa);
            CP16(d + 10240, sl);
        }
        {
            const __nv_bfloat16* sb = Bh + (size_t)br * kKin + kg + bj * 8;
            const __nv_bfloat16* sl = Bl + (size_t)br * kKin + kg + bj * 8;
            uint32_t d = st + 20480 + br * 80 + bj * 16;
            CP16(d, sb);
            CP16(d + 5120, sl);
        }
        CP_COMMIT();
    };

    float acc[2][4][4];
#pragma unroll
    for (int f = 0; f < 2; ++f)
#pragma unroll
        for (int g = 0; g < 4; ++g)
#pragma unroll
            for (int v = 0; v < 4; ++v) acc[f][g][v] = 0.f;

    issue(0, 0);

    for (int kc = 0; kc < 8; ++kc) {
        const int s = kc & 1;
        if (kc < 7) issue(kc + 1, s ^ 1);
        if (kc < 7) CP_WAIT1(); else CP_WAIT0();
        __syncthreads();

        const uint32_t uAh = sbase + s * 30720;
        const uint32_t uAl = uAh + 10240;
        const uint32_t uBh = uAh + 20480;
        const uint32_t uBl = uAh + 25600;
#pragma unroll
        for (int ks = 0; ks < 2; ++ks) {
            const int kb = ks * 16;
            uint32_t ahi[2][4], alo[2][4], bhi[4][2], blo[4][2];
            const int arow = (lid & 15);
            const int akof = kb + ((lid >> 4) << 3);
#pragma unroll
            for (int f = 0; f < 2; ++f) {
                const int m0 = wm * 32 + f * 16;
                uint32_t off = ((m0 + arow) * 40 + akof) * 2;
                ldsm_x4(ahi[f], uAh + off);
                ldsm_x4(alo[f], uAl + off);
            }
            const int brow = (lid & 7);
            const int bkof = kb + (((lid >> 3) & 1) << 3);
#pragma unroll
            for (int g = 0; g < 4; ++g) {
                const int n0 = wn * 32 + g * 8;
                uint32_t off = ((n0 + brow) * 40 + bkof) * 2;
                ldsm_x2(bhi[g], uBh + off);
                ldsm_x2(blo[g], uBl + off);
            }
#pragma unroll
            for (int f = 0; f < 2; ++f)
#pragma unroll
                for (int g = 0; g < 4; ++g) {
                    mma16816(acc[f][g], ahi[f], bhi[g]);
                    mma16816(acc[f][g], alo[f], bhi[g]);
                    mma16816(acc[f][g], ahi[f], blo[g]);
                }
        }
        __syncthreads();
    }

    const size_t yrow = (size_t)(p * 2 + half) * 128;
    const int gr = lid >> 2, tg = lid & 3;
#pragma unroll
    for (int f = 0; f < 2; ++f) {
        const int r0 = wm * 32 + f * 16 + gr;
#pragma unroll
        for (int g = 0; g < 4; ++g) {
            const int col = c0 + wn * 32 + g * 8 + 2 * tg;
            if (col < 722) {
                *(float2*)&g_Y[(yrow + r0) * kColPad + col] =
                    make_float2(acc[f][g][0], acc[f][g][1]);
                *(float2*)&g_Y[(yrow + r0 + 8) * kColPad + col] =
                    make_float2(acc[f][g][2], acc[f][g][3]);
            }
        }
    }
}

// ---------------- Stage D: inverse FFT-360 over lat; out [b][k][lat][q] ----------------
__global__ void __launch_bounds__(TPBF, 4) k_stageD()
{
    __shared__ float2 buf[2][8][361];
    __shared__ float2 s_tw[kNTw];
    const int q0 = blockIdx.x * 8;
    const int bk = blockIdx.y;
    const int b = bk >> 7, k = bk & 127;
    const int tid = threadIdx.x;
    if (tid < kNTw) s_tw[tid] = g_tw[tid];
    for (int e = tid; e < 8 * 360; e += TPBF) {
        int qi = e & 7, p = e >> 3;
        int q = q0 + qi;
        if (q < kNQ) {
            int col = b * 361 + q;
            float yr = g_Y[((size_t)(p * 2 + 0) * 128 + k) * kColPad + col];
            float yi = g_Y[((size_t)(p * 2 + 1) * 128 + k) * kColPad + col];
            buf[0][qi][p] = make_float2(yr, yi);
        } else buf[0][qi][p] = make_float2(0.f, 0.f);
    }
    __syncthreads();
    int res = fft360<8, true, TPBF>(buf, s_tw, tid);
    for (int e = tid; e < 8 * 360; e += TPBF) {
        int qi = e & 7, p = e >> 3;
        int q = q0 + qi;
        if (q < kNQ)
            g_bufA[((size_t)bk * 360 + p) * 361 + q] = buf[res][qi][p];
    }
}

// ---------------- Stage E: inverse real-pack + inverse cfft-360 -> 720 samples ----------------
__global__ void __launch_bounds__(TPBF, 4) k_stageE(float4* __restrict__ out4)
{
    __shared__ float2 buf[2][8][361];
    __shared__ float2 s_tw[kNTw];
    const int row0 = blockIdx.x * 8;
    const int tid = threadIdx.x;
    if (tid < kNTw) s_tw[tid] = g_tw[tid];
    for (int e = tid; e < 8 * 360; e += TPBF) {
        int li = e / 360, k = e - li * 360;
        const float2* src = g_bufA + (size_t)(row0 + li) * 361;
        float2 X1 = src[k];
        float2 X2 = src[360 - k];
        if (k == 0) { X1.y = 0.f; X2.y = 0.f; }   // irfft drops Im(DC), Im(Nyquist)
        float2 E = make_float2(0.5f * (X1.x + X2.x), 0.5f * (X1.y - X2.y));
        float2 D = make_float2(0.5f * (X1.x - X2.x), 0.5f * (X1.y + X2.y));
        float2 pw = g_ptw[k]; pw.y = -pw.y;       // e^{+i pi k/360}
        float2 O = cmulf(pw, D);
        buf[0][li][k] = make_float2(E.x - O.y, E.y + O.x);
    }
    __syncthreads();
    int res = fft360<8, true, TPBF>(buf, s_tw, tid);
    for (int e = tid; e < 8 * 180; e += TPBF) {
        int li = e / 180, j = e - li * 180;
        float2 a = buf[res][li][2 * j];
        float2 b = buf[res][li][2 * j + 1];
        out4[(size_t)(row0 + li) * 180 + j] = make_float4(a.x, a.y, b.x, b.y);
    }
}

extern "C" void kernel_launch(void* const* d_in, const int* in_sizes, int n_in,
                              void* d_out, int out_size)
{
    const float* x = nullptr;
    const float* w = nullptr;
    for (int i = 0; i < n_in; ++i) {
        if (in_sizes[i] == kOutElems)      x = (const float*)d_in[i];
        else if (in_sizes[i] == kWElems)   w = (const float*)d_in[i];
    }
    if (!x) x = (const float*)d_in[0];
    if (!w) w = (const float*)d_in[1];

    constexpr int kSmemB = (2 * 16 * 361 + kNTw) * (int)sizeof(float2);  // 93304
    constexpr int kSmemG = 2 * 30720;                                    // 61440
    cudaFuncSetAttribute(k_stageB,   cudaFuncAttributeMaxDynamicSharedMemorySize, kSmemB);
    cudaFuncSetAttribute(k_gemm_mma, cudaFuncAttributeMaxDynamicSharedMemorySize, kSmemG);

    float4* resid4 = (out_size >= 2 * kOutElems)
                   ? (float4*)((float*)d_out + kOutElems) : nullptr;

    k_prepTw<<< 2, TPB >>>();
    k_prepA <<< dim3(128, 45), TPB >>> (w);
    k_stageA<<< kRows / 8, TPBF >>>((const float4*)x, resid4);
    k_stageB<<< dim3(8, 2, 361), TPBF, kSmemB >>>();
    k_gemm_mma<<< dim3(12, 2, 360), 256, kSmemG >>>();
    k_stageD<<< dim3(46, kB * kC), TPBF >>>();
    k_stageE<<< kRows / 8, TPBF >>>((float4*)d_out);
}